// round 3
// baseline (speedup 1.0000x reference)
#include <cuda_runtime.h>

#define NB 32
#define NPTS 512
#define NC 64
#define PIX (NC * NC)          // 4096
#define ROWS (NPTS + 1)        // 513
#define INV2S2 0.0078125f      // 1/(2*8^2)
#define BG_RATIO 0.15f

// Scratch: factorized exp tables. 2 * 32 * 512 * 64 * 4B = 8 MB (L2-resident).
__device__ float g_Ex[NB][NPTS][NC];
__device__ float g_Ey[NB][NPTS][NC];

// ---------------------------------------------------------------------------
// Kernel 1: Ex[b][n][j] = exp(-(x^2 - 2xc + c^2)/(2 sigma^2)), same for Ey.
// Matches the reference's expansion (not (x-c)^2) for numerics parity.
// ---------------------------------------------------------------------------
__global__ void precompute_kernel(const float* __restrict__ points,
                                  const float* __restrict__ cood) {
    int idx = blockIdx.x * blockDim.x + threadIdx.x;   // over NB*NPTS*NC = 1M
    int j = idx & (NC - 1);
    int n = (idx >> 6) & (NPTS - 1);
    int b = idx >> 15;

    float c = cood[j];
    float x = points[((b * NPTS + n) << 1) + 0];
    float y = points[((b * NPTS + n) << 1) + 1];

    float xd = x * x - 2.0f * x * c + c * c;
    float yd = y * y - 2.0f * y * c + c * c;

    g_Ex[b][n][j] = __expf(-xd * INV2S2);
    g_Ey[b][n][j] = __expf(-yd * INV2S2);
}

// ---------------------------------------------------------------------------
// Kernel 2: one CTA per (batch, 16-row i-tile, 32-col j-tile).
// 256 threads, 2 CTAs/SM (96KB smem each), grid = 32*4*2 = 256.
// Thread owns 2 contiguous j-pixels of one i row.
//
// Pass 1: S_k = sum_n Ey[n,i]*Ex[n,j_k], M_k = max_n (product)
// Finalize: min_dis = max(0, -2s^2 * ln M); bg = (d - sqrt(min_dis))^2
//           denom = S + exp(-bg/2s^2); inv = 1/denom
// Pass 2: out[n, pixel] = Ey*Ex*inv   (softmax without explicit max-shift:
//          identical quotient; underflowed terms are true ~e^-70 zeros)
// ---------------------------------------------------------------------------
#define JT 32
#define IT 16
#define SMEM_BYTES ((NPTS * JT + NPTS * IT) * 4)   // 98304

__global__ __launch_bounds__(256, 2)
void post_prob_kernel(const float* __restrict__ st_sizes,
                      float* __restrict__ out) {
    extern __shared__ float smem[];
    float* sEx = smem;                 // [NPTS][JT]
    float* sEy = smem + NPTS * JT;     // [NPTS][IT]

    int bid = blockIdx.x;
    int b   = bid >> 3;
    int i0  = ((bid >> 1) & 3) << 4;   // 0,16,32,48
    int j0  = (bid & 1) << 5;          // 0,32
    int t   = threadIdx.x;

    // Cooperative smem fill (float4).
    {
        const float* exsrc = &g_Ex[b][0][j0];   // row stride 64 floats
        float4*      exdst = (float4*)sEx;      // row = 8 float4
#pragma unroll
        for (int k = 0; k < 16; k++) {
            int f = t + 256 * k;                // 0..4095
            int n = f >> 3, q = f & 7;
            exdst[f] = *(const float4*)(exsrc + n * NC + q * 4);
        }
        const float* eysrc = &g_Ey[b][0][i0];
        float4*      eydst = (float4*)sEy;      // row = 4 float4
#pragma unroll
        for (int k = 0; k < 8; k++) {
            int f = t + 256 * k;                // 0..2047
            int n = f >> 2, q = f & 3;
            eydst[f] = *(const float4*)(eysrc + n * NC + q * 4);
        }
    }
    __syncthreads();

    int iloc = t >> 4;        // 0..15
    int jg   = t & 15;        // 0..15 -> j = j0 + 2*jg .. +1

    const float2* exv = (const float2*)sEx + jg;   // row stride 16 float2

    float S0 = 0.f, S1 = 0.f;
    float M0 = 0.f, M1 = 0.f;

#pragma unroll 8
    for (int n = 0; n < NPTS; n++) {
        float  ey = sEy[n * IT + iloc];
        float2 ex = exv[n * 16];
        float p0 = ey * ex.x, p1 = ey * ex.y;
        S0 += p0; S1 += p1;
        M0 = fmaxf(M0, p0); M1 = fmaxf(M1, p1);
    }

    float d = st_sizes[b] * BG_RATIO;

    float inv0, inv1, pb0, pb1;
    {
        float m0   = fmaxf(M0, 1e-35f);
        float m1   = fmaxf(M1, 1e-35f);
        float mn0  = fmaxf(-128.0f * __logf(m0), 0.0f);  // 2*sigma^2 = 128
        float mn1  = fmaxf(-128.0f * __logf(m1), 0.0f);
        float bd0  = d - sqrtf(mn0);
        float bd1  = d - sqrtf(mn1);
        float eb0  = __expf(-(bd0 * bd0) * INV2S2);
        float eb1  = __expf(-(bd1 * bd1) * INV2S2);
        inv0 = 1.0f / (S0 + eb0);
        inv1 = 1.0f / (S1 + eb1);
        pb0  = eb0 * inv0;
        pb1  = eb1 * inv1;
    }

    float* obase = out + (size_t)b * ROWS * PIX + (i0 + iloc) * NC + j0 + jg * 2;

    // Background row (row index 512)
    *(float2*)(obase + (size_t)NPTS * PIX) = make_float2(pb0, pb1);

    // Pass 2: stream the 512 point rows
#pragma unroll 8
    for (int n = 0; n < NPTS; n++) {
        float  ey = sEy[n * IT + iloc];
        float2 ex = exv[n * 16];
        float2 o;
        o.x = ey * ex.x * inv0;
        o.y = ey * ex.y * inv1;
        *(float2*)(obase + (size_t)n * PIX) = o;
    }
}

// ---------------------------------------------------------------------------
extern "C" void kernel_launch(void* const* d_in, const int* in_sizes, int n_in,
                              void* d_out, int out_size) {
    const float* points   = (const float*)d_in[0];
    const float* st_sizes = (const float*)d_in[1];
    const float* cood     = (const float*)d_in[2];
    float*       out      = (float*)d_out;

    cudaFuncSetAttribute(post_prob_kernel,
                         cudaFuncAttributeMaxDynamicSharedMemorySize,
                         SMEM_BYTES);

    precompute_kernel<<<(NB * NPTS * NC) / 256, 256>>>(points, cood);
    post_prob_kernel<<<NB * 4 * 2, 256, SMEM_BYTES>>>(st_sizes, out);
}